// round 15
// baseline (speedup 1.0000x reference)
#include <cuda_runtime.h>
#include <cuda_fp16.h>
#include <math.h>

#define B_     16
#define L_     512
#define ENC    7
#define DM     512
#define DIN    1024
#define DSTATE 16
#define DCONV  4
#define DTRANK 32
#define COUT   7
#define PRED   96
#define NROW   (B_*L_)   // 8192
#define BD     (B_*DIN)  // 16384
#define NCH    16        // time chunks
#define CL     (L_/NCH)  // 32 steps per chunk

typedef unsigned long long ull;
typedef unsigned int u32;

// ---------------- scratch (device globals; no allocation) ----------------
__device__ float g_stats[3*B_*ENC];
__device__ float g_pe  [L_*DM];
__device__ __half g_a  [NROW*DM];          // x in fp16
__device__ __half g_b  [2*DIN*DM];         // W_in^T fp16, [n][k]
__device__ __half g_bx [64*DIN];           // W_xproj^T fp16, [n][k]
__device__ __half g_xm [NROW*DIN];         // xz[:, :DIN]  (fp16)
__device__ __half g_z  [NROW*DIN];         // xz[:, DIN:]  (fp16, tail tiles only)
__device__ __half g_uh [NROW*DIN];         // silu(conv(xm)) fp16
__device__ float g_dbc4[4*NROW*64];        // split-K partials (summed inline)
__device__ float g_chS [NCH*BD];           // per-chunk sum(dt)
__device__ __half g_chB [NCH*DSTATE*BD];   // per-chunk b-vector (fp16)
__device__ float g_wc  [DIN*COUT];         // W_out @ W_head

// ---------------- helpers ----------------
__device__ __forceinline__ u32 smem_u32(const void* p){
  u32 a; asm("{ .reg .u64 t; cvta.to.shared.u64 t, %1; cvt.u32.u64 %0, t; }"
             : "=r"(a) : "l"(p)); return a;
}
__device__ __forceinline__ void cp16(u32 dst, const void* src){
  asm volatile("cp.async.cg.shared.global [%0], [%1], 16;" :: "r"(dst), "l"(src) : "memory");
}
#define CP_COMMIT() asm volatile("cp.async.commit_group;" ::: "memory")
#define CP_WAIT0()  asm volatile("cp.async.wait_group 0;" ::: "memory")
#define CP_WAIT1()  asm volatile("cp.async.wait_group 1;" ::: "memory")

#define LDSM_X4(r, a) \
  asm volatile("ldmatrix.sync.aligned.m8n8.x4.shared.b16 {%0,%1,%2,%3}, [%4];" \
    : "=r"((r)[0]),"=r"((r)[1]),"=r"((r)[2]),"=r"((r)[3]) : "r"(a))

#define MMA_F16(d, a, b) \
  asm volatile("mma.sync.aligned.m16n8k16.row.col.f32.f16.f16.f32 " \
    "{%0,%1,%2,%3}, {%4,%5,%6,%7}, {%8,%9}, {%0,%1,%2,%3};" \
    : "+f"((d)[0]),"+f"((d)[1]),"+f"((d)[2]),"+f"((d)[3]) \
    : "r"((a)[0]),"r"((a)[1]),"r"((a)[2]),"r"((a)[3]), "r"((b)[0]),"r"((b)[1]))

__device__ __forceinline__ ull pack2(float x, float y){
  ull r; asm("mov.b64 %0, {%1, %2};" : "=l"(r) : "f"(x), "f"(y)); return r;
}
__device__ __forceinline__ float2 unpack2(ull v){
  float2 f; asm("mov.b64 {%0, %1}, %2;" : "=f"(f.x), "=f"(f.y) : "l"(v)); return f;
}
__device__ __forceinline__ void fma2(ull& d, ull a, ull b){
  asm("fma.rn.f32x2 %0, %1, %2, %0;" : "+l"(d) : "l"(a), "l"(b));
}

// dA[16] from e = exp(dt*A0) when A[n] = -(n+1): dA[n] = e^(n+1)
__device__ __forceinline__ void powchain(float e, float* dA){
  float p2 = e*e, p4 = p2*p2, p8 = p4*p4;
  dA[0]=e;        dA[1]=p2;        dA[2]=p2*e;        dA[3]=p4;
  dA[4]=p4*e;     dA[5]=p4*p2;     dA[6]=p4*p2*e;     dA[7]=p8;
  dA[8]=p8*e;     dA[9]=p8*p2;     dA[10]=p8*p2*e;    dA[11]=p8*p4;
  dA[12]=p8*p4*e; dA[13]=p8*p4*p2; dA[14]=p8*p4*p2*e; dA[15]=p8*p8;
}

// fused dt: softplus(dot(dbc_row[0:32], wdt_col) + b_dt), even/odd packed
__device__ __forceinline__ float dt_eval(const float* srow, const ull* w2, float bdt){
  ull acc = 0ull;
  #pragma unroll
  for (int j = 0; j < 16; j++){
    ull dv = *(const ull*)&srow[2*j];
    fma2(acc, dv, w2[j]);
  }
  float2 s = unpack2(acc);
  float x = s.x + s.y + bdt;
  return x > 20.f ? x : __logf(1.f + __expf(x));
}

// stage one 8-step sub-chunk of dbc (summing the 4 split-K partials inline)
__device__ __forceinline__ void stage_dbc(float* dstRow, size_t rowBase, int tid){
  int row = tid >> 4, col = (tid & 15)*4;
  size_t off = (rowBase + row)*64 + col;
  float4 a = *(const float4*)&g_dbc4[0*NROW*64 + off];
  float4 b = *(const float4*)&g_dbc4[1*NROW*64 + off];
  float4 c = *(const float4*)&g_dbc4[2*NROW*64 + off];
  float4 d = *(const float4*)&g_dbc4[3*NROW*64 + off];
  *(float4*)&dstRow[row*64 + col] =
      make_float4(a.x+b.x+c.x+d.x, a.y+b.y+c.y+d.y,
                  a.z+b.z+c.z+d.z, a.w+b.w+c.w+d.w);
}

// ---------------- prep: coalesced transposes + pe + stats + wcomb -----------
// grid 3248 x 256:
//  [0,1024)    convB  32x32-tile transpose
//  [1024,2048) pe
//  [2048,2112) convXp 32x32-tile transpose
//  [2112,2224) stats
//  [2224,3248) wcomb
__global__ void prep_kernel(const float* __restrict__ x_enc,
                            const float* __restrict__ W_in,
                            const float* __restrict__ W_xproj,
                            const float* __restrict__ W_out,
                            const float* __restrict__ W_head){
  const int bid = blockIdx.x, tid = threadIdx.x;
  if (bid < 1024){
    __shared__ float tile[32][33];
    int tn = bid & 63, tk = bid >> 6;
    int c = tid & 31, r = tid >> 5;
    #pragma unroll
    for (int it = 0; it < 4; it++){
      int k = tk*32 + it*8 + r;
      tile[it*8 + r][c] = W_in[(size_t)k*(2*DIN) + tn*32 + c];
    }
    __syncthreads();
    #pragma unroll
    for (int it = 0; it < 4; it++){
      int n = tn*32 + it*8 + r;
      g_b[(size_t)n*DM + tk*32 + c] = __float2half(tile[c][it*8 + r]);
    }
  } else if (bid < 2048){
    int idx = (bid-1024)*256 + tid;
    int l = idx >> 9, d = idx & (DM-1);
    int p = d >> 1;
    float div = expf((float)(2*p) * (-9.210340371976184f / (float)DM));
    float arg = (float)l * div;
    g_pe[idx] = (d & 1) ? cosf(arg) : sinf(arg);
  } else if (bid < 2112){
    __shared__ float tile[32][33];
    int b2 = bid - 2048;
    int tn = b2 & 1, tk = b2 >> 1;
    int c = tid & 31, r = tid >> 5;
    #pragma unroll
    for (int it = 0; it < 4; it++){
      int k = tk*32 + it*8 + r;
      tile[it*8 + r][c] = W_xproj[(size_t)k*64 + tn*32 + c];
    }
    __syncthreads();
    #pragma unroll
    for (int it = 0; it < 4; it++){
      int n = tn*32 + it*8 + r;
      g_bx[(size_t)n*DIN + tk*32 + c] = __float2half(tile[c][it*8 + r]);
    }
  } else if (bid < 2224){
    int s = bid - 2112;
    int b = s / ENC, c = s % ENC;
    float sum = 0.f, ss = 0.f;
    for (int l = tid; l < L_; l += 256){
      float v = x_enc[(b*L_ + l)*ENC + c];
      sum += v; ss += v*v;
    }
    __shared__ float rs[256], rss[256];
    rs[tid] = sum; rss[tid] = ss; __syncthreads();
    for (int o = 128; o > 0; o >>= 1){
      if (tid < o){ rs[tid] += rs[tid+o]; rss[tid] += rss[tid+o]; }
      __syncthreads();
    }
    if (tid == 0){
      float mean = rs[0] / (float)L_;
      float var  = rss[0] / (float)L_ - mean*mean;
      float stdv = sqrtf(var + 1e-5f);
      g_stats[s]            = mean;
      g_stats[B_*ENC + s]   = stdv;
      g_stats[2*B_*ENC + s] = 1.f / stdv;
    }
  } else {
    int d = bid - 2224;
    if (tid < 224){
      int lane = tid & 31;
      int c    = tid >> 5;
      float acc = 0.f;
      for (int k = lane; k < DM; k += 32)
        acc = fmaf(W_out[(size_t)d*DM + k], W_head[k*COUT + c], acc);
      #pragma unroll
      for (int o = 16; o > 0; o >>= 1) acc += __shfl_xor_sync(0xffffffff, acc, o);
      if (lane == 0) g_wc[d*COUT + c] = acc;
    }
  }
}

// ---------------- embed (+ out mean-init in bx==2 blocks) ----------------
// grid (3, 32, B_), 128 threads
__global__ void embed_kernel(const float* __restrict__ x_enc,
                             const float* __restrict__ W_emb,
                             float* __restrict__ out){
  if (blockIdx.x == 2){
    // init out[b][t][c] = mean[b][c] for t in [ly*3, ly*3+3)
    int ly = blockIdx.y, b = blockIdx.z;
    int idx = threadIdx.x;
    if (idx < 21){
      int tt = idx / 7, c = idx % 7;
      out[((size_t)b*PRED + ly*3 + tt)*COUT + c] = g_stats[b*ENC + c];
    }
    return;
  }
  const int d0 = (blockIdx.x*128 + threadIdx.x)*2;
  const int l0 = blockIdx.y*16;
  const int b  = blockIdx.z;
  __shared__ float sx[18*ENC];
  for (int idx = threadIdx.x; idx < 18*ENC; idx += 128){
    int lr = idx / ENC, c = idx % ENC;
    int ln = (l0 - 1 + lr + L_) & (L_-1);
    sx[idx] = (x_enc[(b*L_ + ln)*ENC + c] - g_stats[b*ENC + c])
            * g_stats[2*B_*ENC + b*ENC + c];
  }
  ull w2[21];
  #pragma unroll
  for (int j = 0; j < 21; j++)
    w2[j] = pack2(W_emb[j*DM + d0], W_emb[j*DM + d0 + 1]);
  __syncthreads();
  #pragma unroll
  for (int li = 0; li < 16; li++){
    float2 pe = *(const float2*)&g_pe[(l0 + li)*DM + d0];
    ull acc = pack2(pe.x, pe.y);
    #pragma unroll
    for (int k = 0; k < 3; k++)
      #pragma unroll
      for (int c = 0; c < ENC; c++){
        float s = sx[(li + k)*ENC + c];
        fma2(acc, pack2(s, s), w2[k*ENC + c]);
      }
    float2 v = unpack2(acc);
    *(__half2*)&g_a[(size_t)(b*L_ + l0 + li)*DM + d0] = __floats2half2_rn(v.x, v.y);
  }
}

// ---------------- mma.sync fp16 GEMM (3-stage pipeline) ----------------
// grid (8, 80): by<64 -> xm tiles; by>=64 -> z for row tile (by-64)*4+3
#define LDK      72
#define ARR_B    (128*LDK*2)
#define STAGE_B  (2*ARR_B)
#define GM_SMEM  (3*STAGE_B)          // 110592

__global__ void __launch_bounds__(256, 2) gemm_mma_kernel(){
  extern __shared__ char smem[];
  const u32 sb = smem_u32(smem);
  const int tid = threadIdx.x, lane = tid & 31, wid = tid >> 5;
  const int warp_m = wid >> 2, warp_n = wid & 3;
  const int by = blockIdx.y;
  const bool isz = by >= 64;
  const int bm = isz ? ((by - 64)*4 + 3)*128 : by*128;
  const int bn = blockIdx.x*128 + (isz ? DIN : 0);

  const __half* srcs[2] = { g_a + (size_t)bm*DM, g_b + (size_t)bn*DM };

  const u32 a_off = ((lane & 15)*LDK + ((lane >> 4) << 3)) * 2;
  const u32 b_off = (((lane & 7) + ((lane >> 4) << 3))*LDK + (((lane >> 3) & 1) << 3)) * 2;

  float acc[4][4][4];
  #pragma unroll
  for (int m = 0; m < 4; m++)
    #pragma unroll
    for (int n = 0; n < 4; n++)
      #pragma unroll
      for (int q = 0; q < 4; q++) acc[m][n][q] = 0.f;

  auto issue = [&](int kc, int stage){
    u32 base = sb + stage*STAGE_B;
    #pragma unroll
    for (int i = 0; i < 8; i++){
      int f = tid + i*256;
      int arr = f >> 10, rem = f & 1023;
      int row = rem >> 3, ch = rem & 7;
      cp16(base + arr*ARR_B + (row*LDK + ch*8)*2,
           srcs[arr] + (size_t)row*DM + kc*64 + ch*8);
    }
    CP_COMMIT();
  };

  issue(0, 0);
  issue(1, 1);
  for (int kc = 0; kc < DM/64; kc++){
    if (kc + 1 < DM/64) CP_WAIT1(); else CP_WAIT0();
    __syncthreads();
    if (kc + 2 < DM/64) issue(kc + 2, (kc + 2) % 3);
    const u32 sA = sb + (kc % 3)*STAGE_B;
    const u32 sB = sA + ARR_B;

    #pragma unroll
    for (int kh = 0; kh < 4; kh++){
      u32 ah[4][4], bh[2][4];
      #pragma unroll
      for (int m = 0; m < 4; m++)
        LDSM_X4(ah[m], sA + a_off + ((warp_m*64 + m*16)*LDK + kh*16)*2);
      #pragma unroll
      for (int p = 0; p < 2; p++)
        LDSM_X4(bh[p], sB + b_off + ((warp_n*32 + p*16)*LDK + kh*16)*2);
      #pragma unroll
      for (int m = 0; m < 4; m++)
        #pragma unroll
        for (int n = 0; n < 4; n++)
          MMA_F16(acc[m][n], ah[m], &bh[n >> 1][(n & 1)*2]);
    }
  }

  __half* dst = isz ? g_z : g_xm;
  const int bnl = bn & (DIN-1);
  const int r_base = bm + warp_m*64 + (lane >> 2);
  const int c_base = bnl + warp_n*32 + (lane & 3)*2;
  #pragma unroll
  for (int m = 0; m < 4; m++)
    #pragma unroll
    for (int n = 0; n < 4; n++){
      int r = r_base + m*16;
      int c = c_base + n*8;
      *(__half2*)&dst[(size_t)r*DIN + c] =
          __floats2half2_rn(acc[m][n][0], acc[m][n][1]);
      *(__half2*)&dst[(size_t)(r+8)*DIN + c] =
          __floats2half2_rn(acc[m][n][2], acc[m][n][3]);
    }
}

// ---------------- xproj via mma: dbc4[z] = u @ W_xproj (split-K x4) ----------
#define XA_B     (128*LDK*2)          // 18432
#define XB_B     (64*LDK*2)           // 9216
#define XSTAGE   (XA_B + XB_B)        // 27648
#define XP_SMEM  (2*XSTAGE)           // 55296

__global__ void __launch_bounds__(256) xproj_mma_kernel(){
  extern __shared__ char smem[];
  const u32 sb = smem_u32(smem);
  const int tid = threadIdx.x, lane = tid & 31, wid = tid >> 5;
  const int warp_m = wid >> 2, warp_n = wid & 3;
  const int bm = blockIdx.x * 128;
  const int z  = blockIdx.y;
  const int k0 = z * 256;

  const __half* srcA = g_uh + (size_t)bm*DIN + k0;
  const __half* srcB = g_bx + k0;

  const u32 a_off = ((lane & 15)*LDK + ((lane >> 4) << 3)) * 2;
  const u32 b_off = (((lane & 7) + ((lane >> 4) << 3))*LDK + (((lane >> 3) & 1) << 3)) * 2;

  float acc[4][2][4];
  #pragma unroll
  for (int m = 0; m < 4; m++)
    #pragma unroll
    for (int n = 0; n < 2; n++)
      #pragma unroll
      for (int q = 0; q < 4; q++) acc[m][n][q] = 0.f;

  auto issue = [&](int kc, int stage){
    u32 base = sb + stage*XSTAGE;
    #pragma unroll
    for (int i = 0; i < 4; i++){
      int f = tid + i*256;
      int row = f >> 3, ch = f & 7;
      cp16(base + (row*LDK + ch*8)*2, srcA + (size_t)row*DIN + kc*64 + ch*8);
    }
    #pragma unroll
    for (int i = 0; i < 2; i++){
      int f = tid + i*256;
      int row = f >> 3, ch = f & 7;
      cp16(base + XA_B + (row*LDK + ch*8)*2, srcB + (size_t)row*DIN + kc*64 + ch*8);
    }
    CP_COMMIT();
  };

  issue(0, 0);
  for (int kc = 0; kc < 4; kc++){
    CP_WAIT0();
    __syncthreads();
    if (kc + 1 < 4) issue(kc + 1, (kc + 1) & 1);
    const u32 sA = sb + (kc & 1)*XSTAGE;
    const u32 sB = sA + XA_B;

    #pragma unroll
    for (int kh = 0; kh < 4; kh++){
      u32 ah[4][4], bh[4];
      #pragma unroll
      for (int m = 0; m < 4; m++)
        LDSM_X4(ah[m], sA + a_off + ((warp_m*64 + m*16)*LDK + kh*16)*2);
      LDSM_X4(bh, sB + b_off + ((warp_n*16)*LDK + kh*16)*2);
      #pragma unroll
      for (int m = 0; m < 4; m++)
        #pragma unroll
        for (int n = 0; n < 2; n++)
          MMA_F16(acc[m][n], ah[m], &bh[n*2]);
    }
  }

  float* dst = g_dbc4 + (size_t)z*NROW*64;
  const int r_base = bm + warp_m*64 + (lane >> 2);
  const int c_base = warp_n*16 + (lane & 3)*2;
  #pragma unroll
  for (int m = 0; m < 4; m++)
    #pragma unroll
    for (int n = 0; n < 2; n++){
      int r = r_base + m*16;
      int c = c_base + n*8;
      *(float2*)&dst[(size_t)r*64 + c]     = make_float2(acc[m][n][0], acc[m][n][1]);
      *(float2*)&dst[(size_t)(r+8)*64 + c] = make_float2(acc[m][n][2], acc[m][n][3]);
    }
}

// ---------------- causal depthwise conv + SiLU (2 d's/thread, f32x2) --------
__global__ void conv_silu_kernel(const float* __restrict__ conv_w,
                                 const float* __restrict__ conv_b){
  int hidx = (blockIdx.x & 1)*256 + threadIdx.x;
  int d0   = hidx*2;
  int rowc = blockIdx.x >> 1;
  int l0   = (rowc & 63) * 8;
  int b    = rowc >> 6;
  const __half2* xm = (const __half2*)g_xm + (size_t)(b*L_)*(DIN/2) + hidx;
  __half2* uo = (__half2*)g_uh + (size_t)(b*L_)*(DIN/2) + hidx;
  ull wp[4];
  #pragma unroll
  for (int k = 0; k < 4; k++)
    wp[k] = pack2(conv_w[k*DIN + d0], conv_w[k*DIN + d0 + 1]);
  const ull bias2 = pack2(conv_b[d0], conv_b[d0 + 1]);
  ull xv[11];
  #pragma unroll
  for (int k = 0; k < 11; k++){
    int l = l0 - 3 + k;
    if (l >= 0){
      float2 v = __half22float2(xm[(size_t)l*(DIN/2)]);
      xv[k] = pack2(v.x, v.y);
    } else xv[k] = 0ull;
  }
  #pragma unroll
  for (int i = 0; i < 8; i++){
    ull acc = bias2;
    fma2(acc, xv[i+0], wp[0]);
    fma2(acc, xv[i+1], wp[1]);
    fma2(acc, xv[i+2], wp[2]);
    fma2(acc, xv[i+3], wp[3]);
    float2 v = unpack2(acc);
    float u0 = v.x * (1.f / (1.f + __expf(-v.x)));
    float u1 = v.y * (1.f / (1.f + __expf(-v.y)));
    uo[(size_t)(l0 + i)*(DIN/2)] = __floats2half2_rn(u0, u1);
  }
}

// ---------------- scan phase 1 (fused dt, inline dbc reduce) ----------------
// grid (8 dchunk, NCH-1 chunks, B_), 128 threads
__global__ void scan1_kernel(const float* __restrict__ A_log,
                             const float* __restrict__ W_dt,
                             const float* __restrict__ b_dt){
  const int tid = threadIdx.x;
  const int d = blockIdx.x*128 + tid;
  const int c = blockIdx.y, b = blockIdx.z;
  __shared__ float sD[2][8][64];

  float A[DSTATE], bv[DSTATE];
  #pragma unroll
  for (int n = 0; n < DSTATE; n++){ A[n] = -expf(A_log[d*DSTATE + n]); bv[n] = 0.f; }
  bool fast = true;
  #pragma unroll
  for (int n = 0; n < DSTATE; n++)
    fast = fast && (fabsf(A[n] + (float)(n+1)) < 1e-3f);
  const float A0 = A[0];
  ull w2[16];
  #pragma unroll
  for (int j = 0; j < 16; j++)
    w2[j] = pack2(W_dt[(2*j)*DIN + d], W_dt[(2*j+1)*DIN + d]);
  const float bdt = b_dt[d];

  const size_t base = (size_t)b*L_ + c*CL;

  stage_dbc(&sD[0][0][0], base, tid);
  float us[8];
  #pragma unroll
  for (int i = 0; i < 8; i++)
    us[i] = __half2float(g_uh[(base+i)*DIN + d]);
  __syncthreads();

  float S = 0.f;
  for (int sc = 0; sc < CL/8; sc++){
    int buf = sc & 1;
    float un[8];
    if (sc+1 < CL/8){
      stage_dbc(&sD[buf^1][0][0], base + (sc+1)*8, tid);
      #pragma unroll
      for (int i = 0; i < 8; i++)
        un[i] = __half2float(g_uh[(base + (sc+1)*8 + i)*DIN + d]);
    }
    #pragma unroll
    for (int tl = 0; tl < 8; tl++){
      float dtv = dt_eval(sD[buf][tl], w2, bdt);
      float coeff = dtv * us[tl];
      float dA[DSTATE];
      if (fast) powchain(__expf(dtv * A0), dA);
      else {
        #pragma unroll
        for (int n = 0; n < DSTATE; n++) dA[n] = __expf(dtv * A[n]);
      }
      #pragma unroll
      for (int n = 0; n < DSTATE; n++)
        bv[n] = fmaf(dA[n], bv[n], coeff * sD[buf][tl][32+n]);
      S += dtv;
    }
    #pragma unroll
    for (int i = 0; i < 8; i++) us[i] = un[i];
    __syncthreads();
  }
  const int ch = b*DIN + d;
  g_chS[c*BD + ch] = S;
  #pragma unroll
  for (int n = 0; n < DSTATE; n++)
    g_chB[(c*DSTATE + n)*BD + ch] = __float2half(bv[n]);
}

// ---------------- scan phase 3: inline prefix + tail y + fused head ---------
// grid (8 dchunk, 3, B_), 128 threads
__global__ void scan3_kernel(const float* __restrict__ A_log,
                             const float* __restrict__ W_dt,
                             const float* __restrict__ b_dt,
                             const float* __restrict__ Dv,
                             float* __restrict__ out){
  const int tid = threadIdx.x;
  const int lane = tid & 31;
  const int d = blockIdx.x*128 + tid;
  const int cc = blockIdx.y, b = blockIdx.z;
  const int t0 = (NCH-3 + cc)*CL;
  __shared__ float sD[2][8][64];

  float A[DSTATE], h[DSTATE];
  #pragma unroll
  for (int n = 0; n < DSTATE; n++){ A[n] = -expf(A_log[d*DSTATE + n]); h[n] = 0.f; }
  bool fast = true;
  #pragma unroll
  for (int n = 0; n < DSTATE; n++)
    fast = fast && (fabsf(A[n] + (float)(n+1)) < 1e-3f);
  const float A0 = A[0];
  const float Dd = Dv[d];
  ull w2[16];
  #pragma unroll
  for (int j = 0; j < 16; j++)
    w2[j] = pack2(W_dt[(2*j)*DIN + d], W_dt[(2*j+1)*DIN + d]);
  const float bdt = b_dt[d];
  const int ch = b*DIN + d;

  // inline prefix over chunks 0..(13+cc-1) to get h at entry of chunk 13+cc
  const int nPref = NCH-3 + cc;
  for (int c = 0; c < nPref; c++){
    float S = g_chS[c*BD + ch];
    float a[DSTATE];
    if (fast) powchain(__expf(S * A0), a);
    else {
      #pragma unroll
      for (int n = 0; n < DSTATE; n++) a[n] = __expf(S * A[n]);
    }
    #pragma unroll
    for (int n = 0; n < DSTATE; n++)
      h[n] = fmaf(a[n], h[n], __half2float(g_chB[(c*DSTATE + n)*BD + ch]));
  }

  // head weights pre-scaled by std
  float wcs[COUT];
  #pragma unroll
  for (int c = 0; c < COUT; c++)
    wcs[c] = g_wc[d*COUT + c] * g_stats[B_*ENC + b*ENC + c];

  const size_t base = (size_t)b*L_ + t0;

  stage_dbc(&sD[0][0][0], base, tid);
  float us[8];
  #pragma unroll
  for (int i = 0; i < 8; i++)
    us[i] = __half2float(g_uh[(base+i)*DIN + d]);
  __syncthreads();

  for (int sc = 0; sc < CL/8; sc++){
    int buf = sc & 1;
    float un[8];
    if (sc+1 < CL/8){
      stage_dbc(&sD[buf^1][0][0], base + (sc+1)*8, tid);
      #pragma unroll
      for (int i = 0; i < 8; i++)
        un[i] = __half2float(g_uh[(base + (sc+1)*8 + i)*DIN + d]);
    }
    #pragma unroll
    for (int tl = 0; tl < 8; tl++){
      int t = t0 + sc*8 + tl;
      float dtv = dt_eval(sD[buf][tl], w2, bdt);
      float uv = us[tl];
      float coeff = dtv * uv;
      float dA[DSTATE];
      if (fast) powchain(__expf(dtv * A0), dA);
      else {
        #pragma unroll
        for (int n = 0; n < DSTATE; n++) dA[n] = __expf(dtv * A[n]);
      }
      float acc = 0.f;
      #pragma unroll
      for (int n = 0; n < DSTATE; n++){
        h[n] = fmaf(dA[n], h[n], coeff * sD[buf][tl][32+n]);
        acc  = fmaf(h[n], sD[buf][tl][48+n], acc);
      }
      float zv  = __half2float(g_z[((size_t)b*L_ + t)*DIN + d]);
      float sig = 1.f / (1.f + __expf(-zv));
      float yv  = (acc + uv*Dd) * (zv * sig);
      // fused head: warp-reduce yv*wcs[c] over 128 d's, atomicAdd into out
      size_t row = (size_t)b*PRED + (t - (L_-PRED));
      #pragma unroll
      for (int c = 0; c < COUT; c++){
        float v = yv * wcs[c];
        #pragma unroll
        for (int o = 16; o > 0; o >>= 1) v += __shfl_xor_sync(0xffffffff, v, o);
        if (lane == 0) atomicAdd(&out[row*COUT + c], v);
      }
    }
    #pragma unroll
    for (int i = 0; i < 8; i++) us[i] = un[i];
    __syncthreads();
  }
}

// ---------------- launch ----------------
extern "C" void kernel_launch(void* const* d_in, const int* in_sizes, int n_in,
                              void* d_out, int out_size){
  const float* x_enc  = (const float*)d_in[0];
  const float* W_emb  = (const float*)d_in[1];
  const float* W_in   = (const float*)d_in[2];
  const float* conv_w = (const float*)d_in[3];
  const float* conv_b = (const float*)d_in[4];
  const float* W_xproj= (const float*)d_in[5];
  const float* W_dt   = (const float*)d_in[6];
  const float* b_dt   = (const float*)d_in[7];
  const float* A_log  = (const float*)d_in[8];
  const float* Dv     = (const float*)d_in[9];
  const float* W_out  = (const float*)d_in[10];
  const float* W_head = (const float*)d_in[11];
  float* out = (float*)d_out;

  static int attr_set = 0;
  if (!attr_set){
    cudaFuncSetAttribute(gemm_mma_kernel,
        cudaFuncAttributeMaxDynamicSharedMemorySize, GM_SMEM);
    cudaFuncSetAttribute(xproj_mma_kernel,
        cudaFuncAttributeMaxDynamicSharedMemorySize, XP_SMEM);
    attr_set = 1;
  }

  prep_kernel<<<3248, 256>>>(x_enc, W_in, W_xproj, W_out, W_head);
  embed_kernel<<<dim3(3, 32, B_), 128>>>(x_enc, W_emb, out);
  gemm_mma_kernel<<<dim3(8, 80), 256, GM_SMEM>>>();
  conv_silu_kernel<<<(NROW/8)*2, 256>>>(conv_w, conv_b);
  xproj_mma_kernel<<<dim3(NROW/128, 4), 256, XP_SMEM>>>();
  scan1_kernel<<<dim3(8, NCH-1, B_), 128>>>(A_log, W_dt, b_dt);
  scan3_kernel<<<dim3(8, 3, B_), 128>>>(A_log, W_dt, b_dt, Dv, out);
}